// round 1
// baseline (speedup 1.0000x reference)
#include <cuda_runtime.h>
#include <math.h>

#define BB 16
#define CC 64
#define SS 128
#define TT 512
#define TSPLIT 32

// ---------------- scratch (static device memory; no runtime allocs) ----------------
static __device__ float g_xT[(size_t)BB*TT*CC*SS];   // [b][t][c][s]  256 MB
static __device__ float g_Y [(size_t)BB*CC*SS*TT];   // [b][c][s][t]  256 MB
static __device__ float g_P [BB*SS*SS];              // attn logits accumulator
static __device__ float g_A [BB*SS*SS];              // softmaxed attn
static __device__ float g_sx[BB*CC*SS];              // sum over t of x
static __device__ float g_t2[BB*SS];
static __device__ float g_t3[BB*SS];
static __device__ float g_r [BB*SS];
static __device__ float g_M [CC*CC];
static __device__ float g_N [CC*CC];
static __device__ float g_u1[CC];
static __device__ float g_u2[CC];
static __device__ float g_g [CC];
static __device__ float g_dotb[1];

// ---------------- prep: small matrices + zero accumulators ----------------
__global__ void prep_kernel(const float* __restrict__ w11, const float* __restrict__ b11,
                            const float* __restrict__ w12, const float* __restrict__ b12,
                            const float* __restrict__ w13, const float* __restrict__ b13,
                            const float* __restrict__ w14, const float* __restrict__ b14) {
    int tid = threadIdx.x;
    int gtid = blockIdx.x * blockDim.x + tid;
    int nthr = blockDim.x * gridDim.x;
    for (int i = gtid; i < BB*SS*SS; i += nthr) g_P[i] = 0.f;
    for (int i = gtid; i < BB*CC*SS; i += nthr) g_sx[i] = 0.f;
    if (blockIdx.x == 0) {
        for (int idx = tid; idx < CC*CC; idx += blockDim.x) {
            int a = idx / CC, e = idx % CC;
            float m = 0.f, n = 0.f;
            for (int c = 0; c < CC; c++) {
                m += w11[c*CC + a] * w12[c*CC + e];   // M = W11^T W12
                n += w14[a*CC + c] * w13[c*CC + e];   // N = W14 W13
            }
            g_M[idx] = m; g_N[idx] = n;
        }
        for (int a = tid; a < CC; a += blockDim.x) {
            float u1 = 0.f, u2 = 0.f, gg = 0.f;
            for (int c = 0; c < CC; c++) {
                u1 += b11[c] * w12[c*CC + a];
                u2 += w11[c*CC + a] * b12[c];
                gg += w14[a*CC + c] * b13[c];
            }
            g_u1[a] = u1; g_u2[a] = u2; g_g[a] = gg;
        }
        if (tid == 0) {
            float d = 0.f;
            for (int c = 0; c < CC; c++) d += b11[c] * b12[c];
            g_dotb[0] = d * (float)TT;
        }
    }
}

// ---------------- transpose: x[b,c,s,t] -> xT[b,t,c,s]; also sum over t ----------------
__global__ void transpose_kernel(const float* __restrict__ x) {
    __shared__ float tile[32][33];
    int t0 = blockIdx.x * 32;
    int s0 = blockIdx.y * 32;
    int bc = blockIdx.z;
    int b = bc / CC, c = bc % CC;
    const float* src = x + ((size_t)(b*CC + c) * SS) * TT;
    int lt = threadIdx.x & 31;
    int lr = threadIdx.x >> 5;    // 0..7
#pragma unroll
    for (int k = 0; k < 4; k++) {
        int sl = lr + 8*k;
        tile[sl][lt] = src[(size_t)(s0 + sl) * TT + t0 + lt];
    }
    __syncthreads();
    if (threadIdx.x < 32) {
        float sum = 0.f;
#pragma unroll
        for (int k = 0; k < 32; k++) sum += tile[threadIdx.x][k];
        atomicAdd(&g_sx[(b*CC + c)*SS + s0 + threadIdx.x], sum);
    }
#pragma unroll
    for (int k = 0; k < 4; k++) {
        int tl = lr + 8*k;
        g_xT[(((size_t)b*TT + t0 + tl) * CC + c) * SS + s0 + lt] = tile[lt][tl];
    }
}

// ---------------- attn logits: P[b] += sum_t X_t^T (M X_t) ----------------
#define A_SMEM ((2*64*132 + 64*64) * 4)
__global__ void __launch_bounds__(256, 1) attn_acc_kernel() {
    extern __shared__ float sm[];
    float* Xs = sm;                 // [64][132]
    float* Ys = sm + 64*132;        // [64][132]
    float* Ms = sm + 2*64*132;      // [64][64]
    int b = blockIdx.x, split = blockIdx.y;
    int tid = threadIdx.x;
    for (int i = tid; i < CC*CC; i += 256) Ms[i] = g_M[i];

    int ty = tid >> 4, tx = tid & 15;
    int i0 = ty*8, j0 = tx*8;
    int s_me = tid & 127, cbase = (tid >> 7) * 32;

    float p[8][8];
#pragma unroll
    for (int r = 0; r < 8; r++)
#pragma unroll
        for (int q = 0; q < 8; q++) p[r][q] = 0.f;

    for (int t = split; t < TT; t += TSPLIT) {
        const float* src = g_xT + ((size_t)b*TT + t) * CC * SS;
        __syncthreads();
        for (int idx = tid; idx < CC*SS/4; idx += 256) {
            int c = idx >> 5, v = idx & 31;
            float4 val = ((const float4*)src)[c*32 + v];
            *(float4*)&Xs[c*132 + v*4] = val;
        }
        __syncthreads();
        // step1: Y = M X
        {
            float acc[32];
#pragma unroll
            for (int k = 0; k < 32; k++) acc[k] = 0.f;
            for (int cp = 0; cp < CC; cp++) {
                float xv = Xs[cp*132 + s_me];
#pragma unroll
                for (int k = 0; k < 32; k++) acc[k] += Ms[(cbase + k)*CC + cp] * xv;
            }
#pragma unroll
            for (int k = 0; k < 32; k++) Ys[(cbase + k)*132 + s_me] = acc[k];
        }
        __syncthreads();
        // step2: P += X^T Y
        for (int c = 0; c < CC; c++) {
            float xa[8], yb[8];
            *(float4*)&xa[0] = *(float4*)&Xs[c*132 + i0];
            *(float4*)&xa[4] = *(float4*)&Xs[c*132 + i0 + 4];
            *(float4*)&yb[0] = *(float4*)&Ys[c*132 + j0];
            *(float4*)&yb[4] = *(float4*)&Ys[c*132 + j0 + 4];
#pragma unroll
            for (int r = 0; r < 8; r++)
#pragma unroll
                for (int q = 0; q < 8; q++) p[r][q] += xa[r] * yb[q];
        }
    }
    float* Pb = g_P + (size_t)b*SS*SS;
#pragma unroll
    for (int r = 0; r < 8; r++)
#pragma unroll
        for (int q = 0; q < 8; q++)
            atomicAdd(&Pb[(i0 + r)*SS + j0 + q], p[r][q]);
}

// ---------------- bias terms for logits ----------------
__global__ void bias_terms_kernel() {
    int b = blockIdx.x, i = threadIdx.x;  // 128 threads
    float t2 = 0.f, t3 = 0.f;
    for (int a = 0; a < CC; a++) {
        float sv = g_sx[(b*CC + a)*SS + i];
        t2 += g_u2[a] * sv;
        t3 += g_u1[a] * sv;
    }
    g_t2[b*SS + i] = t2;
    g_t3[b*SS + i] = t3;
}

// ---------------- softmax_plus1 + rowsums ----------------
__global__ void softmax_kernel() {
    __shared__ float wm[4], ws[4];
    int bid = blockIdx.x;
    int b = bid >> 7, i = bid & 127;
    int j = threadIdx.x;  // 128 threads
    const float inv_scale = 1.0f / sqrtf((float)(CC * TT));
    float v = (g_P[((size_t)b*SS + i)*SS + j] + g_t2[b*SS + i] + g_t3[b*SS + j] + g_dotb[0]) * inv_scale;
    float m = v;
#pragma unroll
    for (int o = 16; o > 0; o >>= 1) m = fmaxf(m, __shfl_xor_sync(0xffffffff, m, o));
    int w = j >> 5, l = j & 31;
    if (l == 0) wm[w] = m;
    __syncthreads();
    m = fmaxf(fmaxf(wm[0], wm[1]), fmaxf(wm[2], wm[3]));
    float e = expf(v - m);
    float s = e;
#pragma unroll
    for (int o = 16; o > 0; o >>= 1) s += __shfl_xor_sync(0xffffffff, s, o);
    if (l == 0) ws[w] = s;
    __syncthreads();
    s = ws[0] + ws[1] + ws[2] + ws[3];
    float denom = 1.0f + s;
    g_A[((size_t)b*SS + i)*SS + j] = e / denom;
    if (j == 0) g_r[b*SS + i] = s / denom;
}

// ---------------- Y = N (x) : 1x1 conv ----------------
#define C1_SMEM ((64*516 + 64*64) * 4)
__global__ void __launch_bounds__(256, 1) convN_kernel(const float* __restrict__ x) {
    extern __shared__ float sm[];
    float* Xs = sm;             // [64][516]
    float* Ns = sm + 64*516;    // [64][64]
    int s = blockIdx.x, b = blockIdx.y;
    int tid = threadIdx.x;
    for (int i = tid; i < CC*CC; i += 256) Ns[i] = g_N[i];
    const float* src = x + ((size_t)(b*CC) * SS + s) * TT;
    for (int idx = tid; idx < CC*TT/4; idx += 256) {
        int c = idx >> 7, v = idx & 127;
        *(float4*)&Xs[c*516 + v*4] = *(const float4*)&src[(size_t)c*SS*TT + v*4];
    }
    __syncthreads();
    int tx = tid & 63, ty = tid >> 6;   // ty 0..3
    float* dst = g_Y + ((size_t)(b*CC) * SS + s) * TT;
    for (int cc = 0; cc < 2; cc++) {
        int c0 = cc*32 + ty*8;
        float acc[8][8];
#pragma unroll
        for (int r = 0; r < 8; r++)
#pragma unroll
            for (int m2 = 0; m2 < 8; m2++) acc[r][m2] = 0.f;
        for (int cp = 0; cp < CC; cp++) {
            float xv[8];
#pragma unroll
            for (int m2 = 0; m2 < 8; m2++) xv[m2] = Xs[cp*516 + tx + 64*m2];
#pragma unroll
            for (int r = 0; r < 8; r++) {
                float nv = Ns[(c0 + r)*CC + cp];
#pragma unroll
                for (int m2 = 0; m2 < 8; m2++) acc[r][m2] += nv * xv[m2];
            }
        }
#pragma unroll
        for (int r = 0; r < 8; r++)
#pragma unroll
            for (int m2 = 0; m2 < 8; m2++)
                dst[(size_t)(c0 + r)*SS*TT + tx + 64*m2] = acc[r][m2];
    }
}

// ---------------- out = alpha*(A Y + r g + b14) + x ----------------
#define C2_SMEM ((128*132 + 128*132) * 4)
__global__ void __launch_bounds__(256, 1) attn_apply_kernel(const float* __restrict__ x,
                                                            const float* __restrict__ alpha,
                                                            const float* __restrict__ b14,
                                                            float* __restrict__ out) {
    extern __shared__ float sm[];
    float* As  = sm;               // [j][i] (transposed), pitch 132
    float* Ysh = sm + 128*132;     // [j][t], pitch 132
    int tk = blockIdx.x, c = blockIdx.y, b = blockIdx.z;
    int t0 = tk * 128;
    int tid = threadIdx.x;

    const float* Ab = g_A + (size_t)b*SS*SS;
    for (int idx = tid; idx < SS*SS; idx += 256) {
        int i = idx >> 7, j = idx & 127;
        As[j*132 + i] = Ab[idx];
    }
    const float* Yb = g_Y + ((size_t)(b*CC + c) * SS) * TT + t0;
    for (int idx = tid; idx < SS*128/4; idx += 256) {
        int j = idx >> 5, v = idx & 31;
        *(float4*)&Ysh[j*132 + v*4] = *(const float4*)&Yb[(size_t)j*TT + v*4];
    }
    __syncthreads();

    int tx = tid & 15, ty = tid >> 4;
    int i0 = ty * 8;
    float o[8][8];
#pragma unroll
    for (int r = 0; r < 8; r++)
#pragma unroll
        for (int q = 0; q < 8; q++) o[r][q] = 0.f;

    for (int j = 0; j < SS; j++) {
        float av[8], yv[8];
        *(float4*)&av[0] = *(float4*)&As[j*132 + i0];
        *(float4*)&av[4] = *(float4*)&As[j*132 + i0 + 4];
#pragma unroll
        for (int m2 = 0; m2 < 8; m2++) yv[m2] = Ysh[j*132 + tx + 16*m2];
#pragma unroll
        for (int r = 0; r < 8; r++)
#pragma unroll
            for (int q = 0; q < 8; q++) o[r][q] += av[r] * yv[q];
    }

    const float* xp = x     + ((size_t)(b*CC + c) * SS) * TT + t0;
    const float* ap = alpha + ((size_t)c * SS) * TT + t0;
    float*       op = out   + ((size_t)(b*CC + c) * SS) * TT + t0;
    float gc = g_g[c], b14c = b14[c];
#pragma unroll
    for (int r = 0; r < 8; r++) {
        int i = i0 + r;
        float rv = g_r[b*SS + i];
#pragma unroll
        for (int m2 = 0; m2 < 8; m2++) {
            int ttv = tx + 16*m2;
            size_t off = (size_t)i*TT + ttv;
            op[off] = ap[off] * (o[r][m2] + rv*gc + b14c) + xp[off];
        }
    }
}

// ---------------- launcher ----------------
extern "C" void kernel_launch(void* const* d_in, const int* in_sizes, int n_in,
                              void* d_out, int out_size) {
    const float* x    = (const float*)d_in[0];
    const float* w11  = (const float*)d_in[1];
    const float* b11  = (const float*)d_in[2];
    const float* w12  = (const float*)d_in[3];
    const float* b12  = (const float*)d_in[4];
    const float* w13  = (const float*)d_in[5];
    const float* b13  = (const float*)d_in[6];
    const float* w14  = (const float*)d_in[7];
    const float* b14  = (const float*)d_in[8];
    const float* alpha= (const float*)d_in[9];
    float* out = (float*)d_out;

    cudaFuncSetAttribute((const void*)attn_acc_kernel,  cudaFuncAttributeMaxDynamicSharedMemorySize, A_SMEM);
    cudaFuncSetAttribute((const void*)convN_kernel,     cudaFuncAttributeMaxDynamicSharedMemorySize, C1_SMEM);
    cudaFuncSetAttribute((const void*)attn_apply_kernel,cudaFuncAttributeMaxDynamicSharedMemorySize, C2_SMEM);

    prep_kernel<<<256, 256>>>(w11, b11, w12, b12, w13, b13, w14, b14);
    transpose_kernel<<<dim3(TT/32, SS/32, BB*CC), 256>>>(x);
    attn_acc_kernel<<<dim3(BB, TSPLIT), 256, A_SMEM>>>();
    bias_terms_kernel<<<BB, 128>>>();
    softmax_kernel<<<BB*SS, 128>>>();
    convN_kernel<<<dim3(SS, BB), 256, C1_SMEM>>>(x);
    attn_apply_kernel<<<dim3(TT/128, CC, BB), 256, C2_SMEM>>>(x, alpha, b14, out);
}